// round 3
// baseline (speedup 1.0000x reference)
#include <cuda_runtime.h>

#define NB 4
#define NXg 432
#define NYg 496
#define Hc 248
#define Wc 216
#define HW (Hc*Wc)
#define C1 8
#define C2 16
#define COUT 400
#define CSP 384
#define KS 15
#define RAD 7
#define NBN (NB*HW)

// scratch (device globals; no allocation allowed)
__device__ float g_hist[NB*NYg*NXg];
__device__ float g_tmp [NB*NYg*NXg];
__device__ float g_dm  [NB*HW];
__device__ float g_c1  [NB*C1*HW];
__device__ float g_c2  [NB*C2*HW];
__device__ float g_gauss[KS];
__device__ int   g_max[NB];              // float bits, values >= 0
__device__ float g_stats1[2*C1];         // sum, sumsq
__device__ float g_stats2[2*C2];
__device__ float g_bn1[2*C1];            // scale, shift
__device__ float g_bn2[2*C2];

// ---------------- concat copy: 384 spatial channels ----------------
// One float4 per thread, streaming load/store (bypass L2 persistence) so the
// concurrently running compute chain keeps its L2 working set.
#define COPY_N (NB*CSP*HW/4)            // 20,570,112 float4s
#define PER_B  (CSP*HW/4)               // 5,142,528 float4s per batch slab
__global__ void k_copy(const float4* __restrict__ src, float4* __restrict__ dst) {
    int i = blockIdx.x*blockDim.x + threadIdx.x;
    if (i >= COPY_N) return;
    int b = i / PER_B;
    int o = i - b*PER_B;
    float4 v = __ldcs(src + i);
    __stcs(dst + (size_t)b*(COUT*HW/4) + o, v);
}

__global__ void k_init() {
    int i = blockIdx.x*blockDim.x + threadIdx.x;
    if (i < NB*NYg*NXg) g_hist[i] = 0.f;
    if (i < KS) {
        const float sig = 6.25f;
        float s = 0.f;
        for (int k = 0; k < KS; k++) {
            float c = (float)(k - RAD);
            s += expf(-c*c/(2.f*sig*sig));
        }
        float c = (float)(i - RAD);
        g_gauss[i] = expf(-c*c/(2.f*sig*sig)) / s;
    }
    if (i < NB)   g_max[i] = 0;
    if (i < 2*C1) g_stats1[i] = 0.f;
    if (i < 2*C2) g_stats2[i] = 0.f;
}

__global__ void k_hist(const float* __restrict__ pts, int n) {
    int i = blockIdx.x*blockDim.x + threadIdx.x;
    if (i >= n) return;
    const float* p = pts + (size_t)i*5;
    int b = (int)p[0];
    int x = (int)__fdiv_rn(p[1] - 0.0f,  0.16f);
    int y = (int)__fdiv_rn(p[2] + 39.68f, 0.16f);
    x = min(max(x, 0), NXg-1);
    y = min(max(y, 0), NYg-1);
    atomicAdd(&g_hist[(b*NYg + y)*NXg + x], 1.0f);
}

__global__ void k_blur_x() {
    int i = blockIdx.x*blockDim.x + threadIdx.x;
    if (i >= NB*NYg*NXg) return;
    int x = i % NXg;
    int row = i / NXg;  // b*NYg + y
    float acc = 0.f;
    #pragma unroll
    for (int k = 0; k < KS; k++) {
        int xx = x + k - RAD;
        if (xx >= 0 && xx < NXg)
            acc += g_gauss[k] * g_hist[row*NXg + xx];
    }
    g_tmp[i] = acc;
}

// blur in y + fused per-batch max (NYg*NXg divisible by 256 -> block never straddles batch)
__global__ void k_blur_y() {
    int i = blockIdx.x*blockDim.x + threadIdx.x;
    int x = i % NXg;
    int y = (i / NXg) % NYg;
    int b = i / (NXg*NYg);
    float acc = 0.f;
    #pragma unroll
    for (int k = 0; k < KS; k++) {
        int yy = y + k - RAD;
        if (yy >= 0 && yy < NYg)
            acc += g_gauss[k] * g_tmp[(b*NYg + yy)*NXg + x];
    }
    g_hist[i] = acc;   // blurred result back into g_hist

    __shared__ float sm[256];
    sm[threadIdx.x] = acc; __syncthreads();
    for (int s = 128; s > 0; s >>= 1) {
        if (threadIdx.x < s) sm[threadIdx.x] = fmaxf(sm[threadIdx.x], sm[threadIdx.x+s]);
        __syncthreads();
    }
    if (threadIdx.x == 0) atomicMax(&g_max[b], __float_as_int(sm[0]));
}

// jax.image.resize 'linear' antialias=True, 2x downsample:
// taps at 2i-1..2i+2 with weights [1,3,3,1], edge-clipped + renormalized.
__device__ __forceinline__ void taps4(int i, int n, int* j, float* w) {
    const float base[4] = {1.f, 3.f, 3.f, 1.f};
    float s = 0.f;
    #pragma unroll
    for (int k = 0; k < 4; k++) {
        int jj = 2*i - 1 + k;
        j[k] = jj;
        if (jj >= 0 && jj < n) { w[k] = base[k]; s += base[k]; }
        else w[k] = 0.f;
    }
    #pragma unroll
    for (int k = 0; k < 4; k++) w[k] /= s;
}

__global__ void k_down() {
    int i = blockIdx.x*blockDim.x + threadIdx.x;
    if (i >= NB*HW) return;
    int x = i % Wc;
    int y = (i / Wc) % Hc;
    int b = i / HW;
    int jy[4], jx[4]; float wy[4], wx[4];
    taps4(y, NYg, jy, wy);
    taps4(x, NXg, jx, wx);
    float acc = 0.f;
    #pragma unroll
    for (int a = 0; a < 4; a++) {
        if (wy[a] == 0.f) continue;
        float r = 0.f;
        #pragma unroll
        for (int c = 0; c < 4; c++) {
            if (wx[c] == 0.f) continue;
            r += wx[c] * g_hist[(b*NYg + jy[a])*NXg + jx[c]];
        }
        acc += wy[a] * r;
    }
    float mx = __int_as_float(g_max[b]);
    g_dm[i] = (mx > 0.f) ? acc / mx : acc;
}

__global__ void k_conv1(const float* __restrict__ w1) {
    int bc = blockIdx.y;                 // b*C1 + c
    int b = bc / C1, c = bc % C1;
    int hw = blockIdx.x*blockDim.x + threadIdx.x;
    float v = 0.f;
    if (hw < HW) {
        int x = hw % Wc, y = hw / Wc;
        const float* wp = w1 + c*9;
        const float* in = g_dm + b*HW;
        #pragma unroll
        for (int dy = 0; dy < 3; dy++) {
            int yy = y + dy - 1;
            if (yy < 0 || yy >= Hc) continue;
            #pragma unroll
            for (int dx = 0; dx < 3; dx++) {
                int xx = x + dx - 1;
                if (xx < 0 || xx >= Wc) continue;
                v = fmaf(__ldg(&wp[dy*3+dx]), in[yy*Wc+xx], v);
            }
        }
        g_c1[bc*HW + hw] = v;
    }
    __shared__ float s1[256], s2[256];
    float vv = (hw < HW) ? v : 0.f;
    s1[threadIdx.x] = vv; s2[threadIdx.x] = vv*vv;
    __syncthreads();
    for (int s = 128; s > 0; s >>= 1) {
        if (threadIdx.x < s) { s1[threadIdx.x] += s1[threadIdx.x+s]; s2[threadIdx.x] += s2[threadIdx.x+s]; }
        __syncthreads();
    }
    if (threadIdx.x == 0) {
        atomicAdd(&g_stats1[c], s1[0]);
        atomicAdd(&g_stats1[C1 + c], s2[0]);
    }
}

__global__ void k_bnp1(const float* __restrict__ gamma, const float* __restrict__ beta) {
    int c = threadIdx.x;
    if (c >= C1) return;
    float mean = g_stats1[c] / (float)NBN;
    float var  = g_stats1[C1+c] / (float)NBN - mean*mean;
    float inv  = rsqrtf(var + 1e-3f);
    float sc   = gamma[c] * inv;
    g_bn1[c] = sc;
    g_bn1[C1+c] = beta[c] - mean*sc;
}

__global__ void k_relu1() {
    int i = blockIdx.x*blockDim.x + threadIdx.x;
    if (i >= NB*C1*HW) return;
    int c = (i / HW) % C1;
    g_c1[i] = fmaxf(fmaf(g_c1[i], g_bn1[c], g_bn1[C1+c]), 0.f);
}

__global__ void k_conv2(const float* __restrict__ w2) {
    int bc = blockIdx.y;                 // b*C2 + co
    int b = bc / C2, co = bc % C2;
    __shared__ float ws[C1*9];
    if (threadIdx.x < C1*9) ws[threadIdx.x] = w2[co*C1*9 + threadIdx.x];
    __syncthreads();
    int hw = blockIdx.x*blockDim.x + threadIdx.x;
    float v = 0.f;
    if (hw < HW) {
        int x = hw % Wc, y = hw / Wc;
        #pragma unroll
        for (int ci = 0; ci < C1; ci++) {
            const float* in = g_c1 + (b*C1 + ci)*HW;
            const float* wp = ws + ci*9;
            #pragma unroll
            for (int dy = 0; dy < 3; dy++) {
                int yy = y + dy - 1;
                if (yy < 0 || yy >= Hc) continue;
                #pragma unroll
                for (int dx = 0; dx < 3; dx++) {
                    int xx = x + dx - 1;
                    if (xx < 0 || xx >= Wc) continue;
                    v = fmaf(wp[dy*3+dx], in[yy*Wc+xx], v);
                }
            }
        }
        g_c2[bc*HW + hw] = v;
    }
    __shared__ float s1[256], s2[256];
    float vv = (hw < HW) ? v : 0.f;
    s1[threadIdx.x] = vv; s2[threadIdx.x] = vv*vv;
    __syncthreads();
    for (int s = 128; s > 0; s >>= 1) {
        if (threadIdx.x < s) { s1[threadIdx.x] += s1[threadIdx.x+s]; s2[threadIdx.x] += s2[threadIdx.x+s]; }
        __syncthreads();
    }
    if (threadIdx.x == 0) {
        atomicAdd(&g_stats2[co], s1[0]);
        atomicAdd(&g_stats2[C2 + co], s2[0]);
    }
}

__global__ void k_bnp2(const float* __restrict__ gamma, const float* __restrict__ beta) {
    int c = threadIdx.x;
    if (c >= C2) return;
    float mean = g_stats2[c] / (float)NBN;
    float var  = g_stats2[C2+c] / (float)NBN - mean*mean;
    float inv  = rsqrtf(var + 1e-3f);
    float sc   = gamma[c] * inv;
    g_bn2[c] = sc;
    g_bn2[C2+c] = beta[c] - mean*sc;
}

__global__ void k_out(float* __restrict__ out) {
    int i = blockIdx.x*blockDim.x + threadIdx.x;
    if (i >= NB*C2*HW) return;
    int hw = i % HW;
    int c  = (i / HW) % C2;
    int b  = i / (C2*HW);
    float v = fmaxf(fmaf(g_c2[i], g_bn2[c], g_bn2[C2+c]), 0.f);
    out[((size_t)b*COUT + CSP + c)*HW + hw] = v;
}

extern "C" void kernel_launch(void* const* d_in, const int* in_sizes, int n_in,
                              void* d_out, int out_size) {
    const float* spatial = (const float*)d_in[0];
    const float* points  = (const float*)d_in[1];
    const float* w1      = (const float*)d_in[2];
    const float* gamma1  = (const float*)d_in[3];
    const float* beta1   = (const float*)d_in[4];
    const float* w2      = (const float*)d_in[5];
    const float* gamma2  = (const float*)d_in[6];
    const float* beta2   = (const float*)d_in[7];
    float* out = (float*)d_out;
    int npts = in_sizes[1] / 5;

    // NON-BLOCKING side stream: does NOT implicitly sync with the legacy
    // default stream, so the captured graph gets a真 parallel branch.
    static cudaStream_t s_copy = [](){
        cudaStream_t t; cudaStreamCreateWithFlags(&t, cudaStreamNonBlocking); return t;
    }();
    static cudaEvent_t ev_fork = [](){ cudaEvent_t e; cudaEventCreateWithFlags(&e, cudaEventDisableTiming); return e; }();
    static cudaEvent_t ev_join = [](){ cudaEvent_t e; cudaEventCreateWithFlags(&e, cudaEventDisableTiming); return e; }();

    // Fork: concat copy of the 384 spatial channels runs concurrently with the chain.
    cudaEventRecord(ev_fork, 0);
    cudaStreamWaitEvent(s_copy, ev_fork, 0);
    k_copy<<<(COPY_N + 255)/256, 256, 0, s_copy>>>((const float4*)spatial, (float4*)out);
    cudaEventRecord(ev_join, s_copy);

    int total = NB*NYg*NXg;
    k_init  <<<(total + 255)/256, 256>>>();
    k_hist  <<<(npts + 255)/256, 256>>>(points, npts);
    k_blur_x<<<(total + 255)/256, 256>>>();
    k_blur_y<<<total/256, 256>>>();
    k_down  <<<(NB*HW + 255)/256, 256>>>();
    { dim3 g((HW + 255)/256, NB*C1); k_conv1<<<g, 256>>>(w1); }
    k_bnp1  <<<1, 32>>>(gamma1, beta1);
    k_relu1 <<<(NB*C1*HW + 255)/256, 256>>>();
    { dim3 g((HW + 255)/256, NB*C2); k_conv2<<<g, 256>>>(w2); }
    k_bnp2  <<<1, 32>>>(gamma2, beta2);
    k_out   <<<(NB*C2*HW + 255)/256, 256>>>(out);

    // Join: graph sink depends on both branches.
    cudaStreamWaitEvent(0, ev_join, 0);
}

// round 4
// speedup vs baseline: 1.0082x; 1.0082x over previous
#include <cuda_runtime.h>

#define NB 4
#define NXg 432
#define NYg 496
#define Hc 248
#define Wc 216
#define HW (Hc*Wc)
#define C1 8
#define C2 16
#define COUT 400
#define CSP 384
#define KS 15
#define RAD 7
#define NBN (NB*HW)

// scratch (device globals; no allocation allowed)
__device__ float g_hist[NB*NYg*NXg];
__device__ float g_tmp [NB*NYg*NXg];
__device__ float g_dm  [NB*HW];
__device__ float g_c1  [NB*C1*HW];
__device__ float g_c2  [NB*C2*HW];
__device__ float g_gauss[KS];
__device__ int   g_max[NB];              // float bits, values >= 0
__device__ float g_stats1[2*C1];         // sum, sumsq
__device__ float g_stats2[2*C2];

// ---------------- concat copy: 384 spatial channels ----------------
// dst[i + b*214272] = src[i]  (214272 = 16*HW/4 extra float4s per batch in dst)
// Each block owns a contiguous 1024-float4 (4KB) chunk; blocks never straddle a
// batch (PER_B = 5,142,528 divisible by 1024). Each thread: 4 independent
// float4 loads (MLP=4) then 4 stores, streaming (.cs) both ways.
#define COPY_N  (NB*CSP*HW/4)            // 20,570,112 float4s
#define PER_B   (CSP*HW/4)               // 5,142,528
#define CPB     1024                     // float4s per block
#define NBLK_PB (PER_B/CPB)              // 5022
#define DSKIP   ((COUT-CSP)*HW/4)        // 214,272
__global__ void k_copy(const float4* __restrict__ src, float4* __restrict__ dst) {
    int blk = blockIdx.x;
    int b = blk / NBLK_PB;
    size_t s = (size_t)blk*CPB + threadIdx.x;
    size_t d = s + (size_t)b*DSKIP;
    float4 v0 = __ldcs(src + s);
    float4 v1 = __ldcs(src + s + 256);
    float4 v2 = __ldcs(src + s + 512);
    float4 v3 = __ldcs(src + s + 768);
    __stcs(dst + d,       v0);
    __stcs(dst + d + 256, v1);
    __stcs(dst + d + 512, v2);
    __stcs(dst + d + 768, v3);
}

__global__ void k_init() {
    int i = blockIdx.x*blockDim.x + threadIdx.x;
    if (i < NB*NYg*NXg) g_hist[i] = 0.f;
    if (i < KS) {
        const float sig = 6.25f;
        float s = 0.f;
        for (int k = 0; k < KS; k++) {
            float c = (float)(k - RAD);
            s += expf(-c*c/(2.f*sig*sig));
        }
        float c = (float)(i - RAD);
        g_gauss[i] = expf(-c*c/(2.f*sig*sig)) / s;
    }
    if (i < NB)   g_max[i] = 0;
    if (i < 2*C1) g_stats1[i] = 0.f;
    if (i < 2*C2) g_stats2[i] = 0.f;
}

__global__ void k_hist(const float* __restrict__ pts, int n) {
    int i = blockIdx.x*blockDim.x + threadIdx.x;
    if (i >= n) return;
    const float* p = pts + (size_t)i*5;
    int b = (int)p[0];
    int x = (int)__fdiv_rn(p[1] - 0.0f,  0.16f);
    int y = (int)__fdiv_rn(p[2] + 39.68f, 0.16f);
    x = min(max(x, 0), NXg-1);
    y = min(max(y, 0), NYg-1);
    atomicAdd(&g_hist[(b*NYg + y)*NXg + x], 1.0f);
}

__global__ void k_blur_x() {
    int i = blockIdx.x*blockDim.x + threadIdx.x;
    if (i >= NB*NYg*NXg) return;
    int x = i % NXg;
    int row = i / NXg;  // b*NYg + y
    float acc = 0.f;
    #pragma unroll
    for (int k = 0; k < KS; k++) {
        int xx = x + k - RAD;
        if (xx >= 0 && xx < NXg)
            acc += g_gauss[k] * g_hist[row*NXg + xx];
    }
    g_tmp[i] = acc;
}

// blur in y + fused per-batch max (NYg*NXg divisible by 256 -> block never straddles batch)
__global__ void k_blur_y() {
    int i = blockIdx.x*blockDim.x + threadIdx.x;
    int x = i % NXg;
    int y = (i / NXg) % NYg;
    int b = i / (NXg*NYg);
    float acc = 0.f;
    #pragma unroll
    for (int k = 0; k < KS; k++) {
        int yy = y + k - RAD;
        if (yy >= 0 && yy < NYg)
            acc += g_gauss[k] * g_tmp[(b*NYg + yy)*NXg + x];
    }
    g_hist[i] = acc;   // blurred result back into g_hist

    __shared__ float sm[256];
    sm[threadIdx.x] = acc; __syncthreads();
    for (int s = 128; s > 0; s >>= 1) {
        if (threadIdx.x < s) sm[threadIdx.x] = fmaxf(sm[threadIdx.x], sm[threadIdx.x+s]);
        __syncthreads();
    }
    if (threadIdx.x == 0) atomicMax(&g_max[b], __float_as_int(sm[0]));
}

// jax.image.resize 'linear' antialias=True, 2x downsample:
// taps at 2i-1..2i+2 with weights [1,3,3,1], edge-clipped + renormalized.
__device__ __forceinline__ void taps4(int i, int n, int* j, float* w) {
    const float base[4] = {1.f, 3.f, 3.f, 1.f};
    float s = 0.f;
    #pragma unroll
    for (int k = 0; k < 4; k++) {
        int jj = 2*i - 1 + k;
        j[k] = jj;
        if (jj >= 0 && jj < n) { w[k] = base[k]; s += base[k]; }
        else w[k] = 0.f;
    }
    #pragma unroll
    for (int k = 0; k < 4; k++) w[k] /= s;
}

__global__ void k_down() {
    int i = blockIdx.x*blockDim.x + threadIdx.x;
    if (i >= NB*HW) return;
    int x = i % Wc;
    int y = (i / Wc) % Hc;
    int b = i / HW;
    int jy[4], jx[4]; float wy[4], wx[4];
    taps4(y, NYg, jy, wy);
    taps4(x, NXg, jx, wx);
    float acc = 0.f;
    #pragma unroll
    for (int a = 0; a < 4; a++) {
        if (wy[a] == 0.f) continue;
        float r = 0.f;
        #pragma unroll
        for (int c = 0; c < 4; c++) {
            if (wx[c] == 0.f) continue;
            r += wx[c] * g_hist[(b*NYg + jy[a])*NXg + jx[c]];
        }
        acc += wy[a] * r;
    }
    float mx = __int_as_float(g_max[b]);
    g_dm[i] = (mx > 0.f) ? acc / mx : acc;
}

__global__ void k_conv1(const float* __restrict__ w1) {
    int bc = blockIdx.y;                 // b*C1 + c
    int b = bc / C1, c = bc % C1;
    int hw = blockIdx.x*blockDim.x + threadIdx.x;
    float v = 0.f;
    if (hw < HW) {
        int x = hw % Wc, y = hw / Wc;
        const float* wp = w1 + c*9;
        const float* in = g_dm + b*HW;
        #pragma unroll
        for (int dy = 0; dy < 3; dy++) {
            int yy = y + dy - 1;
            if (yy < 0 || yy >= Hc) continue;
            #pragma unroll
            for (int dx = 0; dx < 3; dx++) {
                int xx = x + dx - 1;
                if (xx < 0 || xx >= Wc) continue;
                v = fmaf(__ldg(&wp[dy*3+dx]), in[yy*Wc+xx], v);
            }
        }
        g_c1[bc*HW + hw] = v;
    }
    __shared__ float s1[256], s2[256];
    float vv = (hw < HW) ? v : 0.f;
    s1[threadIdx.x] = vv; s2[threadIdx.x] = vv*vv;
    __syncthreads();
    for (int s = 128; s > 0; s >>= 1) {
        if (threadIdx.x < s) { s1[threadIdx.x] += s1[threadIdx.x+s]; s2[threadIdx.x] += s2[threadIdx.x+s]; }
        __syncthreads();
    }
    if (threadIdx.x == 0) {
        atomicAdd(&g_stats1[c], s1[0]);
        atomicAdd(&g_stats1[C1 + c], s2[0]);
    }
}

// BN1 affine computed per-block from finished stats (bnp1 kernel removed), then relu.
__global__ void k_relu1(const float* __restrict__ gamma, const float* __restrict__ beta) {
    __shared__ float sc[C1], sh[C1];
    if (threadIdx.x < C1) {
        int c = threadIdx.x;
        float mean = g_stats1[c] / (float)NBN;
        float var  = g_stats1[C1+c] / (float)NBN - mean*mean;
        float s    = gamma[c] * rsqrtf(var + 1e-3f);
        sc[c] = s; sh[c] = beta[c] - mean*s;
    }
    __syncthreads();
    int i = blockIdx.x*blockDim.x + threadIdx.x;
    if (i >= NB*C1*HW) return;
    int c = (i / HW) % C1;
    g_c1[i] = fmaxf(fmaf(g_c1[i], sc[c], sh[c]), 0.f);
}

__global__ void k_conv2(const float* __restrict__ w2) {
    int bc = blockIdx.y;                 // b*C2 + co
    int b = bc / C2, co = bc % C2;
    __shared__ float ws[C1*9];
    if (threadIdx.x < C1*9) ws[threadIdx.x] = w2[co*C1*9 + threadIdx.x];
    __syncthreads();
    int hw = blockIdx.x*blockDim.x + threadIdx.x;
    float v = 0.f;
    if (hw < HW) {
        int x = hw % Wc, y = hw / Wc;
        #pragma unroll
        for (int ci = 0; ci < C1; ci++) {
            const float* in = g_c1 + (b*C1 + ci)*HW;
            const float* wp = ws + ci*9;
            #pragma unroll
            for (int dy = 0; dy < 3; dy++) {
                int yy = y + dy - 1;
                if (yy < 0 || yy >= Hc) continue;
                #pragma unroll
                for (int dx = 0; dx < 3; dx++) {
                    int xx = x + dx - 1;
                    if (xx < 0 || xx >= Wc) continue;
                    v = fmaf(wp[dy*3+dx], in[yy*Wc+xx], v);
                }
            }
        }
        g_c2[bc*HW + hw] = v;
    }
    __shared__ float s1[256], s2[256];
    float vv = (hw < HW) ? v : 0.f;
    s1[threadIdx.x] = vv; s2[threadIdx.x] = vv*vv;
    __syncthreads();
    for (int s = 128; s > 0; s >>= 1) {
        if (threadIdx.x < s) { s1[threadIdx.x] += s1[threadIdx.x+s]; s2[threadIdx.x] += s2[threadIdx.x+s]; }
        __syncthreads();
    }
    if (threadIdx.x == 0) {
        atomicAdd(&g_stats2[co], s1[0]);
        atomicAdd(&g_stats2[C2 + co], s2[0]);
    }
}

// BN2 affine computed per-block (bnp2 removed), relu, scatter into concat slot.
__global__ void k_out(float* __restrict__ out,
                      const float* __restrict__ gamma, const float* __restrict__ beta) {
    __shared__ float sc[C2], sh[C2];
    if (threadIdx.x < C2) {
        int c = threadIdx.x;
        float mean = g_stats2[c] / (float)NBN;
        float var  = g_stats2[C2+c] / (float)NBN - mean*mean;
        float s    = gamma[c] * rsqrtf(var + 1e-3f);
        sc[c] = s; sh[c] = beta[c] - mean*s;
    }
    __syncthreads();
    int i = blockIdx.x*blockDim.x + threadIdx.x;
    if (i >= NB*C2*HW) return;
    int hw = i % HW;
    int c  = (i / HW) % C2;
    int b  = i / (C2*HW);
    float v = fmaxf(fmaf(g_c2[i], sc[c], sh[c]), 0.f);
    out[((size_t)b*COUT + CSP + c)*HW + hw] = v;
}

extern "C" void kernel_launch(void* const* d_in, const int* in_sizes, int n_in,
                              void* d_out, int out_size) {
    const float* spatial = (const float*)d_in[0];
    const float* points  = (const float*)d_in[1];
    const float* w1      = (const float*)d_in[2];
    const float* gamma1  = (const float*)d_in[3];
    const float* beta1   = (const float*)d_in[4];
    const float* w2      = (const float*)d_in[5];
    const float* gamma2  = (const float*)d_in[6];
    const float* beta2   = (const float*)d_in[7];
    float* out = (float*)d_out;
    int npts = in_sizes[1] / 5;

    static cudaStream_t s_copy = [](){
        cudaStream_t t; cudaStreamCreateWithFlags(&t, cudaStreamNonBlocking); return t;
    }();
    static cudaEvent_t ev_fork = [](){ cudaEvent_t e; cudaEventCreateWithFlags(&e, cudaEventDisableTiming); return e; }();
    static cudaEvent_t ev_join = [](){ cudaEvent_t e; cudaEventCreateWithFlags(&e, cudaEventDisableTiming); return e; }();

    // Fork: concat copy of the 384 spatial channels runs concurrently with the chain.
    cudaEventRecord(ev_fork, 0);
    cudaStreamWaitEvent(s_copy, ev_fork, 0);
    k_copy<<<COPY_N/CPB, 256, 0, s_copy>>>((const float4*)spatial, (float4*)out);
    cudaEventRecord(ev_join, s_copy);

    int total = NB*NYg*NXg;
    k_init  <<<(total + 255)/256, 256>>>();
    k_hist  <<<(npts + 255)/256, 256>>>(points, npts);
    k_blur_x<<<(total + 255)/256, 256>>>();
    k_blur_y<<<total/256, 256>>>();
    k_down  <<<(NB*HW + 255)/256, 256>>>();
    { dim3 g((HW + 255)/256, NB*C1); k_conv1<<<g, 256>>>(w1); }
    k_relu1 <<<(NB*C1*HW + 255)/256, 256>>>(gamma1, beta1);
    { dim3 g((HW + 255)/256, NB*C2); k_conv2<<<g, 256>>>(w2); }
    k_out   <<<(NB*C2*HW + 255)/256, 256>>>(out, gamma2, beta2);

    // Join: graph sink depends on both branches.
    cudaStreamWaitEvent(0, ev_join, 0);
}

// round 5
// speedup vs baseline: 1.1140x; 1.1050x over previous
#include <cuda_runtime.h>

#define NB 4
#define NXg 432
#define NYg 496
#define Hc 248
#define Wc 216
#define HW (Hc*Wc)
#define C1 8
#define C2 16
#define COUT 400
#define CSP 384
#define KS 15
#define RAD 7
#define NBN (NB*HW)

// scratch (device globals; no allocation allowed)
__device__ float g_hist[NB*NYg*NXg];
__device__ float g_tmp [NB*NYg*NXg];
__device__ float g_dm  [NB*HW];
__device__ float g_c1  [NB*C1*HW];
__device__ float g_c2  [NB*C2*HW];
__device__ float g_gauss[KS];
__device__ int   g_max[NB];              // float bits, values >= 0
__device__ float g_stats1[2*C1];         // sum, sumsq
__device__ float g_stats2[2*C2];

// ---------------- concat copy, distributed across the chain kernels ----------------
// dst[i + b*DSKIP] = src[i]; shares partition [0, COPY_N).
#define COPY_N  (NB*CSP*HW/4)            // 20,570,112 float4s
#define PER_B   (CSP*HW/4)               // 5,142,528
#define DSKIP   ((COUT-CSP)*HW/4)        // 214,272

// copy shares per kernel (sum == COPY_N)
#define S_INIT  2500000
#define S_HIST  2500000
#define S_BLX   3000000
#define S_BLY   3000000
#define S_DOWN  1500000
#define S_CV1   3000000
#define S_CV2   4000000
#define S_OUT   (COPY_N - S_INIT - S_HIST - S_BLX - S_BLY - S_DOWN - S_CV1 - S_CV2)
#define O_INIT  0
#define O_HIST  (O_INIT + S_INIT)
#define O_BLX   (O_HIST + S_HIST)
#define O_BLY   (O_BLX + S_BLX)
#define O_DOWN  (O_BLY + S_BLY)
#define O_CV1   (O_DOWN + S_DOWN)
#define O_CV2   (O_CV1 + S_CV1)
#define O_OUT   (O_CV2 + S_CV2)

__device__ __forceinline__ void copy_share(const float4* __restrict__ src,
                                           float4* __restrict__ dst,
                                           int start, int count) {
    int tid = ((blockIdx.y*gridDim.x + blockIdx.x)*blockDim.x) + threadIdx.x;
    int nth = gridDim.x*gridDim.y*blockDim.x;
    for (int i = start + tid; i < start + count; i += nth) {
        int b = i / PER_B;
        float4 v = __ldcs(src + i);
        __stcs(dst + i + b*DSKIP, v);
    }
}

__global__ void k_init(const float4* __restrict__ cs, float4* __restrict__ cd) {
    int i = blockIdx.x*blockDim.x + threadIdx.x;
    if (i < NB*NYg*NXg) g_hist[i] = 0.f;
    if (i < KS) {
        const float sig = 6.25f;
        float s = 0.f;
        for (int k = 0; k < KS; k++) {
            float c = (float)(k - RAD);
            s += expf(-c*c/(2.f*sig*sig));
        }
        float c = (float)(i - RAD);
        g_gauss[i] = expf(-c*c/(2.f*sig*sig)) / s;
    }
    if (i < NB)   g_max[i] = 0;
    if (i < 2*C1) g_stats1[i] = 0.f;
    if (i < 2*C2) g_stats2[i] = 0.f;
    copy_share(cs, cd, O_INIT, S_INIT);
}

__global__ void k_hist(const float* __restrict__ pts, int n,
                       const float4* __restrict__ cs, float4* __restrict__ cd) {
    int i = blockIdx.x*blockDim.x + threadIdx.x;
    if (i < n) {
        const float* p = pts + (size_t)i*5;
        int b = (int)p[0];
        int x = (int)__fdiv_rn(p[1] - 0.0f,  0.16f);
        int y = (int)__fdiv_rn(p[2] + 39.68f, 0.16f);
        x = min(max(x, 0), NXg-1);
        y = min(max(y, 0), NYg-1);
        atomicAdd(&g_hist[(b*NYg + y)*NXg + x], 1.0f);
    }
    copy_share(cs, cd, O_HIST, S_HIST);
}

__global__ void k_blur_x(const float4* __restrict__ cs, float4* __restrict__ cd) {
    int i = blockIdx.x*blockDim.x + threadIdx.x;
    if (i < NB*NYg*NXg) {
        int x = i % NXg;
        int row = i / NXg;  // b*NYg + y
        float acc = 0.f;
        #pragma unroll
        for (int k = 0; k < KS; k++) {
            int xx = x + k - RAD;
            if (xx >= 0 && xx < NXg)
                acc += g_gauss[k] * g_hist[row*NXg + xx];
        }
        g_tmp[i] = acc;
    }
    copy_share(cs, cd, O_BLX, S_BLX);
}

// blur in y + fused per-batch max (NYg*NXg divisible by 256 -> block never straddles batch)
__global__ void k_blur_y(const float4* __restrict__ cs, float4* __restrict__ cd) {
    int i = blockIdx.x*blockDim.x + threadIdx.x;
    int x = i % NXg;
    int y = (i / NXg) % NYg;
    int b = i / (NXg*NYg);
    float acc = 0.f;
    #pragma unroll
    for (int k = 0; k < KS; k++) {
        int yy = y + k - RAD;
        if (yy >= 0 && yy < NYg)
            acc += g_gauss[k] * g_tmp[(b*NYg + yy)*NXg + x];
    }
    g_hist[i] = acc;   // blurred result back into g_hist

    __shared__ float sm[256];
    sm[threadIdx.x] = acc; __syncthreads();
    for (int s = 128; s > 0; s >>= 1) {
        if (threadIdx.x < s) sm[threadIdx.x] = fmaxf(sm[threadIdx.x], sm[threadIdx.x+s]);
        __syncthreads();
    }
    if (threadIdx.x == 0) atomicMax(&g_max[b], __float_as_int(sm[0]));
    copy_share(cs, cd, O_BLY, S_BLY);
}

// jax.image.resize 'linear' antialias=True, 2x downsample:
// taps at 2i-1..2i+2 with weights [1,3,3,1], edge-clipped + renormalized.
__device__ __forceinline__ void taps4(int i, int n, int* j, float* w) {
    const float base[4] = {1.f, 3.f, 3.f, 1.f};
    float s = 0.f;
    #pragma unroll
    for (int k = 0; k < 4; k++) {
        int jj = 2*i - 1 + k;
        j[k] = jj;
        if (jj >= 0 && jj < n) { w[k] = base[k]; s += base[k]; }
        else w[k] = 0.f;
    }
    #pragma unroll
    for (int k = 0; k < 4; k++) w[k] /= s;
}

__global__ void k_down(const float4* __restrict__ cs, float4* __restrict__ cd) {
    int i = blockIdx.x*blockDim.x + threadIdx.x;
    if (i < NB*HW) {
        int x = i % Wc;
        int y = (i / Wc) % Hc;
        int b = i / HW;
        int jy[4], jx[4]; float wy[4], wx[4];
        taps4(y, NYg, jy, wy);
        taps4(x, NXg, jx, wx);
        float acc = 0.f;
        #pragma unroll
        for (int a = 0; a < 4; a++) {
            if (wy[a] != 0.f) {
                float r = 0.f;
                #pragma unroll
                for (int c = 0; c < 4; c++) {
                    if (wx[c] != 0.f)
                        r += wx[c] * g_hist[(b*NYg + jy[a])*NXg + jx[c]];
                }
                acc += wy[a] * r;
            }
        }
        float mx = __int_as_float(g_max[b]);
        g_dm[i] = (mx > 0.f) ? acc / mx : acc;
    }
    copy_share(cs, cd, O_DOWN, S_DOWN);
}

__global__ void k_conv1(const float* __restrict__ w1,
                        const float4* __restrict__ cs, float4* __restrict__ cd) {
    int bc = blockIdx.y;                 // b*C1 + c
    int b = bc / C1, c = bc % C1;
    int hw = blockIdx.x*blockDim.x + threadIdx.x;
    float v = 0.f;
    if (hw < HW) {
        int x = hw % Wc, y = hw / Wc;
        const float* wp = w1 + c*9;
        const float* in = g_dm + b*HW;
        #pragma unroll
        for (int dy = 0; dy < 3; dy++) {
            int yy = y + dy - 1;
            if (yy < 0 || yy >= Hc) continue;
            #pragma unroll
            for (int dx = 0; dx < 3; dx++) {
                int xx = x + dx - 1;
                if (xx < 0 || xx >= Wc) continue;
                v = fmaf(__ldg(&wp[dy*3+dx]), in[yy*Wc+xx], v);
            }
        }
        g_c1[bc*HW + hw] = v;
    }
    __shared__ float s1[256], s2[256];
    float vv = (hw < HW) ? v : 0.f;
    s1[threadIdx.x] = vv; s2[threadIdx.x] = vv*vv;
    __syncthreads();
    for (int s = 128; s > 0; s >>= 1) {
        if (threadIdx.x < s) { s1[threadIdx.x] += s1[threadIdx.x+s]; s2[threadIdx.x] += s2[threadIdx.x+s]; }
        __syncthreads();
    }
    if (threadIdx.x == 0) {
        atomicAdd(&g_stats1[c], s1[0]);
        atomicAdd(&g_stats1[C1 + c], s2[0]);
    }
    copy_share(cs, cd, O_CV1, S_CV1);
}

// conv2 with BN1+ReLU applied inline to the raw conv1 output (k_relu1 removed).
__global__ void k_conv2(const float* __restrict__ w2,
                        const float* __restrict__ gamma1, const float* __restrict__ beta1,
                        const float4* __restrict__ cs, float4* __restrict__ cd) {
    int bc = blockIdx.y;                 // b*C2 + co
    int b = bc / C2, co = bc % C2;
    __shared__ float ws[C1*9];
    __shared__ float sc1[C1], sh1[C1];
    if (threadIdx.x < C1*9) ws[threadIdx.x] = w2[co*C1*9 + threadIdx.x];
    if (threadIdx.x < C1) {
        int c = threadIdx.x;
        float mean = g_stats1[c] / (float)NBN;
        float var  = g_stats1[C1+c] / (float)NBN - mean*mean;
        float s    = gamma1[c] * rsqrtf(var + 1e-3f);
        sc1[c] = s; sh1[c] = beta1[c] - mean*s;
    }
    __syncthreads();
    int hw = blockIdx.x*blockDim.x + threadIdx.x;
    float v = 0.f;
    if (hw < HW) {
        int x = hw % Wc, y = hw / Wc;
        #pragma unroll
        for (int ci = 0; ci < C1; ci++) {
            const float* in = g_c1 + (b*C1 + ci)*HW;
            const float* wp = ws + ci*9;
            float a = sc1[ci], s0 = sh1[ci];
            #pragma unroll
            for (int dy = 0; dy < 3; dy++) {
                int yy = y + dy - 1;
                if (yy < 0 || yy >= Hc) continue;
                #pragma unroll
                for (int dx = 0; dx < 3; dx++) {
                    int xx = x + dx - 1;
                    if (xx < 0 || xx >= Wc) continue;
                    float t = fmaxf(fmaf(in[yy*Wc+xx], a, s0), 0.f);
                    v = fmaf(wp[dy*3+dx], t, v);
                }
            }
        }
        g_c2[bc*HW + hw] = v;
    }
    __shared__ float s1[256], s2[256];
    float vv = (hw < HW) ? v : 0.f;
    s1[threadIdx.x] = vv; s2[threadIdx.x] = vv*vv;
    __syncthreads();
    for (int s = 128; s > 0; s >>= 1) {
        if (threadIdx.x < s) { s1[threadIdx.x] += s1[threadIdx.x+s]; s2[threadIdx.x] += s2[threadIdx.x+s]; }
        __syncthreads();
    }
    if (threadIdx.x == 0) {
        atomicAdd(&g_stats2[co], s1[0]);
        atomicAdd(&g_stats2[C2 + co], s2[0]);
    }
    copy_share(cs, cd, O_CV2, S_CV2);
}

// BN2 affine computed per-block, relu, scatter into concat slot.
__global__ void k_out(float* __restrict__ out,
                      const float* __restrict__ gamma, const float* __restrict__ beta,
                      const float4* __restrict__ cs, float4* __restrict__ cd) {
    __shared__ float sc[C2], sh[C2];
    if (threadIdx.x < C2) {
        int c = threadIdx.x;
        float mean = g_stats2[c] / (float)NBN;
        float var  = g_stats2[C2+c] / (float)NBN - mean*mean;
        float s    = gamma[c] * rsqrtf(var + 1e-3f);
        sc[c] = s; sh[c] = beta[c] - mean*s;
    }
    __syncthreads();
    int i = blockIdx.x*blockDim.x + threadIdx.x;
    if (i < NB*C2*HW) {
        int hw = i % HW;
        int c  = (i / HW) % C2;
        int b  = i / (C2*HW);
        float v = fmaxf(fmaf(g_c2[i], sc[c], sh[c]), 0.f);
        out[((size_t)b*COUT + CSP + c)*HW + hw] = v;
    }
    copy_share(cs, cd, O_OUT, S_OUT);
}

extern "C" void kernel_launch(void* const* d_in, const int* in_sizes, int n_in,
                              void* d_out, int out_size) {
    const float* spatial = (const float*)d_in[0];
    const float* points  = (const float*)d_in[1];
    const float* w1      = (const float*)d_in[2];
    const float* gamma1  = (const float*)d_in[3];
    const float* beta1   = (const float*)d_in[4];
    const float* w2      = (const float*)d_in[5];
    const float* gamma2  = (const float*)d_in[6];
    const float* beta2   = (const float*)d_in[7];
    float* out = (float*)d_out;
    int npts = in_sizes[1] / 5;

    const float4* cs = (const float4*)spatial;
    float4* cd = (float4*)out;

    int total = NB*NYg*NXg;
    k_init  <<<(total + 255)/256, 256>>>(cs, cd);
    k_hist  <<<(npts + 255)/256, 256>>>(points, npts, cs, cd);
    k_blur_x<<<(total + 255)/256, 256>>>(cs, cd);
    k_blur_y<<<total/256, 256>>>(cs, cd);
    k_down  <<<(NB*HW + 255)/256, 256>>>(cs, cd);
    { dim3 g((HW + 255)/256, NB*C1); k_conv1<<<g, 256>>>(w1, cs, cd); }
    { dim3 g((HW + 255)/256, NB*C2); k_conv2<<<g, 256>>>(w2, gamma1, beta1, cs, cd); }
    k_out   <<<(NB*C2*HW + 255)/256, 256>>>(out, gamma2, beta2, cs, cd);
}

// round 6
// speedup vs baseline: 1.1270x; 1.0116x over previous
#include <cuda_runtime.h>

#define NB 4
#define NXg 432
#define NYg 496
#define Hc 248
#define Wc 216
#define HW (Hc*Wc)
#define C1 8
#define C2 16
#define COUT 400
#define CSP 384
#define KS 15
#define RAD 7
#define NBN (NB*HW)

// scratch (device globals; no allocation allowed)
__device__ float g_hist[NB*NYg*NXg];
__device__ float g_tmp [NB*NYg*NXg];
__device__ float g_dm  [NB*HW];
__device__ float g_c1  [NB*C1*HW];
__device__ float g_c2  [NB*C2*HW];
__device__ float g_gauss[KS];
__device__ int   g_max[NB];              // float bits, values >= 0
__device__ float g_stats1[2*C1];         // sum, sumsq
__device__ float g_stats2[2*C2];

// ---------------- concat copy, software-pipelined through the chain ----------------
// dst[i + (i/PER_B)*DSKIP] = src[i], i in [0, COPY_N). Each thread: up to 4
// independent streaming loads in the PROLOGUE (MLP=4, latency hidden behind the
// kernel's compute), 4 streaming stores in the EPILOGUE.
#define COPY_N  (NB*CSP*HW/4)            // 20,570,112 float4s
#define PER_B   (CSP*HW/4)               // 5,142,528
#define DSKIP   ((COUT-CSP)*HW/4)        // 214,272

// shares (sum == COPY_N); per-kernel 4*threads >= share verified:
//  init 3,428,352>=3e6  hist 1,600,512>=1.2e6  blx/bly 3,428,352>=3e6
//  down 857,088>=8e5    conv1 6,881,280>=6e6   out 13,713,408>=3,570,112
#define S_INIT  3000000
#define S_HIST  1200000
#define S_BLX   3000000
#define S_BLY   3000000
#define S_DOWN  800000
#define S_CV1   6000000
#define S_OUT   (COPY_N - S_INIT - S_HIST - S_BLX - S_BLY - S_DOWN - S_CV1)
#define O_INIT  0
#define O_HIST  (O_INIT + S_INIT)
#define O_BLX   (O_HIST + S_HIST)
#define O_BLY   (O_BLX + S_BLX)
#define O_DOWN  (O_BLY + S_BLY)
#define O_CV1   (O_DOWN + S_DOWN)
#define O_OUT   (O_CV1 + S_CV1)

struct CopyCtx { float4 v[4]; int idx[4]; };

__device__ __forceinline__ void copy_pro(const float4* __restrict__ src,
                                         int start, int count, CopyCtx& c) {
    int tid = ((blockIdx.y*gridDim.x + blockIdx.x)*blockDim.x) + threadIdx.x;
    int nth = gridDim.x*gridDim.y*blockDim.x;
    int end = start + count;
    #pragma unroll
    for (int k = 0; k < 4; k++) {
        int i = start + tid + k*nth;
        c.idx[k] = (i < end) ? i : -1;
    }
    #pragma unroll
    for (int k = 0; k < 4; k++)
        if (c.idx[k] >= 0) c.v[k] = __ldcs(src + c.idx[k]);
}

__device__ __forceinline__ void copy_epi(float4* __restrict__ dst, const CopyCtx& c) {
    #pragma unroll
    for (int k = 0; k < 4; k++)
        if (c.idx[k] >= 0) {
            int b = c.idx[k] / PER_B;
            __stcs(dst + c.idx[k] + b*DSKIP, c.v[k]);
        }
}

__global__ void k_init(const float4* __restrict__ cs, float4* __restrict__ cd) {
    CopyCtx cc; copy_pro(cs, O_INIT, S_INIT, cc);
    int i = blockIdx.x*blockDim.x + threadIdx.x;
    if (i < NB*NYg*NXg) g_hist[i] = 0.f;
    if (i < KS) {
        const float sig = 6.25f;
        float s = 0.f;
        for (int k = 0; k < KS; k++) {
            float c = (float)(k - RAD);
            s += expf(-c*c/(2.f*sig*sig));
        }
        float c = (float)(i - RAD);
        g_gauss[i] = expf(-c*c/(2.f*sig*sig)) / s;
    }
    if (i < NB)   g_max[i] = 0;
    if (i < 2*C1) g_stats1[i] = 0.f;
    if (i < 2*C2) g_stats2[i] = 0.f;
    copy_epi(cd, cc);
}

__global__ void k_hist(const float* __restrict__ pts, int n,
                       const float4* __restrict__ cs, float4* __restrict__ cd) {
    CopyCtx cc; copy_pro(cs, O_HIST, S_HIST, cc);
    int i = blockIdx.x*blockDim.x + threadIdx.x;
    if (i < n) {
        const float* p = pts + (size_t)i*5;
        int b = (int)p[0];
        int x = (int)__fdiv_rn(p[1] - 0.0f,  0.16f);
        int y = (int)__fdiv_rn(p[2] + 39.68f, 0.16f);
        x = min(max(x, 0), NXg-1);
        y = min(max(y, 0), NYg-1);
        atomicAdd(&g_hist[(b*NYg + y)*NXg + x], 1.0f);
    }
    copy_epi(cd, cc);
}

__global__ void k_blur_x(const float4* __restrict__ cs, float4* __restrict__ cd) {
    CopyCtx cc; copy_pro(cs, O_BLX, S_BLX, cc);
    int i = blockIdx.x*blockDim.x + threadIdx.x;
    if (i < NB*NYg*NXg) {
        int x = i % NXg;
        int row = i / NXg;  // b*NYg + y
        float acc = 0.f;
        #pragma unroll
        for (int k = 0; k < KS; k++) {
            int xx = x + k - RAD;
            if (xx >= 0 && xx < NXg)
                acc += g_gauss[k] * g_hist[row*NXg + xx];
        }
        g_tmp[i] = acc;
    }
    copy_epi(cd, cc);
}

// blur in y + fused per-batch max (NYg*NXg divisible by 256 -> block never straddles batch)
__global__ void k_blur_y(const float4* __restrict__ cs, float4* __restrict__ cd) {
    CopyCtx cc; copy_pro(cs, O_BLY, S_BLY, cc);
    int i = blockIdx.x*blockDim.x + threadIdx.x;
    int x = i % NXg;
    int y = (i / NXg) % NYg;
    int b = i / (NXg*NYg);
    float acc = 0.f;
    #pragma unroll
    for (int k = 0; k < KS; k++) {
        int yy = y + k - RAD;
        if (yy >= 0 && yy < NYg)
            acc += g_gauss[k] * g_tmp[(b*NYg + yy)*NXg + x];
    }
    g_hist[i] = acc;   // blurred result back into g_hist

    __shared__ float sm[256];
    sm[threadIdx.x] = acc; __syncthreads();
    for (int s = 128; s > 0; s >>= 1) {
        if (threadIdx.x < s) sm[threadIdx.x] = fmaxf(sm[threadIdx.x], sm[threadIdx.x+s]);
        __syncthreads();
    }
    if (threadIdx.x == 0) atomicMax(&g_max[b], __float_as_int(sm[0]));
    copy_epi(cd, cc);
}

// jax.image.resize 'linear' antialias=True, 2x downsample:
// taps at 2i-1..2i+2 with weights [1,3,3,1], edge-clipped + renormalized.
__device__ __forceinline__ void taps4(int i, int n, int* j, float* w) {
    const float base[4] = {1.f, 3.f, 3.f, 1.f};
    float s = 0.f;
    #pragma unroll
    for (int k = 0; k < 4; k++) {
        int jj = 2*i - 1 + k;
        j[k] = jj;
        if (jj >= 0 && jj < n) { w[k] = base[k]; s += base[k]; }
        else w[k] = 0.f;
    }
    #pragma unroll
    for (int k = 0; k < 4; k++) w[k] /= s;
}

__global__ void k_down(const float4* __restrict__ cs, float4* __restrict__ cd) {
    CopyCtx cc; copy_pro(cs, O_DOWN, S_DOWN, cc);
    int i = blockIdx.x*blockDim.x + threadIdx.x;
    if (i < NB*HW) {
        int x = i % Wc;
        int y = (i / Wc) % Hc;
        int b = i / HW;
        int jy[4], jx[4]; float wy[4], wx[4];
        taps4(y, NYg, jy, wy);
        taps4(x, NXg, jx, wx);
        float acc = 0.f;
        #pragma unroll
        for (int a = 0; a < 4; a++) {
            if (wy[a] != 0.f) {
                float r = 0.f;
                #pragma unroll
                for (int c = 0; c < 4; c++) {
                    if (wx[c] != 0.f)
                        r += wx[c] * g_hist[(b*NYg + jy[a])*NXg + jx[c]];
                }
                acc += wy[a] * r;
            }
        }
        float mx = __int_as_float(g_max[b]);
        g_dm[i] = (mx > 0.f) ? acc / mx : acc;
    }
    copy_epi(cd, cc);
}

__global__ void k_conv1(const float* __restrict__ w1,
                        const float4* __restrict__ cs, float4* __restrict__ cd) {
    CopyCtx cc; copy_pro(cs, O_CV1, S_CV1, cc);
    int bc = blockIdx.y;                 // b*C1 + c
    int b = bc / C1, c = bc % C1;
    int hw = blockIdx.x*blockDim.x + threadIdx.x;
    float v = 0.f;
    if (hw < HW) {
        int x = hw % Wc, y = hw / Wc;
        const float* wp = w1 + c*9;
        const float* in = g_dm + b*HW;
        #pragma unroll
        for (int dy = 0; dy < 3; dy++) {
            int yy = y + dy - 1;
            if (yy < 0 || yy >= Hc) continue;
            #pragma unroll
            for (int dx = 0; dx < 3; dx++) {
                int xx = x + dx - 1;
                if (xx < 0 || xx >= Wc) continue;
                v = fmaf(__ldg(&wp[dy*3+dx]), in[yy*Wc+xx], v);
            }
        }
        g_c1[bc*HW + hw] = v;
    }
    __shared__ float s1[256], s2[256];
    float vv = (hw < HW) ? v : 0.f;
    s1[threadIdx.x] = vv; s2[threadIdx.x] = vv*vv;
    __syncthreads();
    for (int s = 128; s > 0; s >>= 1) {
        if (threadIdx.x < s) { s1[threadIdx.x] += s1[threadIdx.x+s]; s2[threadIdx.x] += s2[threadIdx.x+s]; }
        __syncthreads();
    }
    if (threadIdx.x == 0) {
        atomicAdd(&g_stats1[c], s1[0]);
        atomicAdd(&g_stats1[C1 + c], s2[0]);
    }
    copy_epi(cd, cc);
}

// conv2 with BN1+ReLU applied inline to raw conv1 output. No copy share:
// this is the longest pure-compute kernel; the bytes ride in the others.
__global__ void k_conv2(const float* __restrict__ w2,
                        const float* __restrict__ gamma1, const float* __restrict__ beta1) {
    int bc = blockIdx.y;                 // b*C2 + co
    int b = bc / C2, co = bc % C2;
    __shared__ float ws[C1*9];
    __shared__ float sc1[C1], sh1[C1];
    if (threadIdx.x < C1*9) ws[threadIdx.x] = w2[co*C1*9 + threadIdx.x];
    if (threadIdx.x < C1) {
        int c = threadIdx.x;
        float mean = g_stats1[c] / (float)NBN;
        float var  = g_stats1[C1+c] / (float)NBN - mean*mean;
        float s    = gamma1[c] * rsqrtf(var + 1e-3f);
        sc1[c] = s; sh1[c] = beta1[c] - mean*s;
    }
    __syncthreads();
    int hw = blockIdx.x*blockDim.x + threadIdx.x;
    float v = 0.f;
    if (hw < HW) {
        int x = hw % Wc, y = hw / Wc;
        #pragma unroll
        for (int ci = 0; ci < C1; ci++) {
            const float* in = g_c1 + (b*C1 + ci)*HW;
            const float* wp = ws + ci*9;
            float a = sc1[ci], s0 = sh1[ci];
            #pragma unroll
            for (int dy = 0; dy < 3; dy++) {
                int yy = y + dy - 1;
                if (yy < 0 || yy >= Hc) continue;
                #pragma unroll
                for (int dx = 0; dx < 3; dx++) {
                    int xx = x + dx - 1;
                    if (xx < 0 || xx >= Wc) continue;
                    float t = fmaxf(fmaf(in[yy*Wc+xx], a, s0), 0.f);
                    v = fmaf(wp[dy*3+dx], t, v);
                }
            }
        }
        g_c2[bc*HW + hw] = v;
    }
    __shared__ float s1[256], s2[256];
    float vv = (hw < HW) ? v : 0.f;
    s1[threadIdx.x] = vv; s2[threadIdx.x] = vv*vv;
    __syncthreads();
    for (int s = 128; s > 0; s >>= 1) {
        if (threadIdx.x < s) { s1[threadIdx.x] += s1[threadIdx.x+s]; s2[threadIdx.x] += s2[threadIdx.x+s]; }
        __syncthreads();
    }
    if (threadIdx.x == 0) {
        atomicAdd(&g_stats2[co], s1[0]);
        atomicAdd(&g_stats2[C2 + co], s2[0]);
    }
}

// BN2 affine computed per-block, relu, scatter into concat slot.
__global__ void k_out(float* __restrict__ out,
                      const float* __restrict__ gamma, const float* __restrict__ beta,
                      const float4* __restrict__ cs, float4* __restrict__ cd) {
    CopyCtx cc; copy_pro(cs, O_OUT, S_OUT, cc);
    __shared__ float sc[C2], sh[C2];
    if (threadIdx.x < C2) {
        int c = threadIdx.x;
        float mean = g_stats2[c] / (float)NBN;
        float var  = g_stats2[C2+c] / (float)NBN - mean*mean;
        float s    = gamma[c] * rsqrtf(var + 1e-3f);
        sc[c] = s; sh[c] = beta[c] - mean*s;
    }
    __syncthreads();
    int i = blockIdx.x*blockDim.x + threadIdx.x;
    if (i < NB*C2*HW) {
        int hw = i % HW;
        int c  = (i / HW) % C2;
        int b  = i / (C2*HW);
        float v = fmaxf(fmaf(g_c2[i], sc[c], sh[c]), 0.f);
        out[((size_t)b*COUT + CSP + c)*HW + hw] = v;
    }
    copy_epi(cd, cc);
}

extern "C" void kernel_launch(void* const* d_in, const int* in_sizes, int n_in,
                              void* d_out, int out_size) {
    const float* spatial = (const float*)d_in[0];
    const float* points  = (const float*)d_in[1];
    const float* w1      = (const float*)d_in[2];
    const float* gamma1  = (const float*)d_in[3];
    const float* beta1   = (const float*)d_in[4];
    const float* w2      = (const float*)d_in[5];
    const float* gamma2  = (const float*)d_in[6];
    const float* beta2   = (const float*)d_in[7];
    float* out = (float*)d_out;
    int npts = in_sizes[1] / 5;

    const float4* cs = (const float4*)spatial;
    float4* cd = (float4*)out;

    int total = NB*NYg*NXg;
    k_init  <<<(total + 255)/256, 256>>>(cs, cd);
    k_hist  <<<(npts + 255)/256, 256>>>(points, npts, cs, cd);
    k_blur_x<<<(total + 255)/256, 256>>>(cs, cd);
    k_blur_y<<<total/256, 256>>>(cs, cd);
    k_down  <<<(NB*HW + 255)/256, 256>>>(cs, cd);
    { dim3 g((HW + 255)/256, NB*C1); k_conv1<<<g, 256>>>(w1, cs, cd); }
    { dim3 g((HW + 255)/256, NB*C2); k_conv2<<<g, 256>>>(w2, gamma1, beta1); }
    k_out   <<<(NB*C2*HW + 255)/256, 256>>>(out, gamma2, beta2, cs, cd);
}